// round 7
// baseline (speedup 1.0000x reference)
#include <cuda_runtime.h>
#include <math.h>

// Problem dims (fixed by the dataset)
#define Td 1024
#define Bd 16
#define Hd 1024
#define Sd 2048
#define BHd (Bd*Hd)   // 16384

// GEMM tiling
#define BM 128
#define BN 128
#define BK 8

typedef unsigned long long u64;

// Scratch for context (T,B,H) fp32 = 64MB. Static device global (no allocs allowed).
__device__ float g_ctx[(size_t)Td * Bd * Hd];

// ---------------------------------------------------------------------------
// Packed f32x2 helpers (sm_100+ PTX; ptxas will not auto-fuse these)
// ---------------------------------------------------------------------------
__device__ __forceinline__ u64 pack2(float lo, float hi) {
    u64 r; asm("mov.b64 %0, {%1, %2};" : "=l"(r) : "f"(lo), "f"(hi)); return r;
}
__device__ __forceinline__ void unpack2(u64 v, float& lo, float& hi) {
    asm("mov.b64 {%0, %1}, %2;" : "=f"(lo), "=f"(hi) : "l"(v));
}
__device__ __forceinline__ u64 ffma2(u64 a, u64 b, u64 c) {
    u64 d; asm("fma.rn.f32x2 %0, %1, %2, %3;" : "=l"(d) : "l"(a), "l"(b), "l"(c));
    return d;
}

// ---------------------------------------------------------------------------
// Shared micro-kernel: 8x8 FMA block (as 8x4 packed pairs) on one k-slice.
// acc[i][jp] holds columns (2*jp, 2*jp+1) for row i.
// ---------------------------------------------------------------------------
__device__ __forceinline__ void micro_fma(
    const float (*As)[BM], const float (*Bs)[BN],
    int tty, int ttx, u64 acc[8][4])
{
#pragma unroll
    for (int k = 0; k < BK; k++) {
        float4 a0 = *(const float4*)&As[k][tty * 8];
        float4 a1 = *(const float4*)&As[k][tty * 8 + 4];
        float4 b0 = *(const float4*)&Bs[k][ttx * 8];
        float4 b1 = *(const float4*)&Bs[k][ttx * 8 + 4];
        u64 ad[8];
        ad[0] = pack2(a0.x, a0.x); ad[1] = pack2(a0.y, a0.y);
        ad[2] = pack2(a0.z, a0.z); ad[3] = pack2(a0.w, a0.w);
        ad[4] = pack2(a1.x, a1.x); ad[5] = pack2(a1.y, a1.y);
        ad[6] = pack2(a1.z, a1.z); ad[7] = pack2(a1.w, a1.w);
        u64 bp[4];
        bp[0] = pack2(b0.x, b0.y); bp[1] = pack2(b0.z, b0.w);
        bp[2] = pack2(b1.x, b1.y); bp[3] = pack2(b1.z, b1.w);
#pragma unroll
        for (int i = 0; i < 8; i++)
#pragma unroll
            for (int jp = 0; jp < 4; jp++)
                acc[i][jp] = ffma2(ad[i], bp[jp], acc[i][jp]);
    }
}

__device__ __forceinline__ void zero_acc(u64 acc[8][4]) {
#pragma unroll
    for (int i = 0; i < 8; i++)
#pragma unroll
        for (int jp = 0; jp < 4; jp++) acc[i][jp] = 0ULL;
}

// Store one row of 8 accumulated columns (4 pairs) as two float4s.
__device__ __forceinline__ void store_row(float* cp, const u64 a[4]) {
    float r[8];
    unpack2(a[0], r[0], r[1]); unpack2(a[1], r[2], r[3]);
    unpack2(a[2], r[4], r[5]); unpack2(a[3], r[6], r[7]);
    *(float4*)(cp)     = make_float4(r[0], r[1], r[2], r[3]);
    *(float4*)(cp + 4) = make_float4(r[4], r[5], r[6], r[7]);
}

// ---------------------------------------------------------------------------
// K1: scores[b,t,s] = sum_h output[t,b,h] * memory[s,b,h]   (NT GEMM per batch)
// Double-buffered smem pipeline; writes raw scores into attn region of d_out.
// ---------------------------------------------------------------------------
__global__ __launch_bounds__(256) void gemm_scores(
    const float* __restrict__ outp, const float* __restrict__ mem,
    float* __restrict__ attn)
{
    const int b = blockIdx.z;
    const float* A  = outp + b * Hd;              // row t, stride BHd, k=h contiguous
    const float* Bm = mem  + b * Hd;              // row s, stride BHd, k=h contiguous
    float* C = attn + (size_t)b * Td * Sd;        // row t, stride Sd

    __shared__ float As[2][BK][BM];
    __shared__ float Bs[2][BK][BN];

    const int tid = threadIdx.x;
    const int m0 = blockIdx.y * BM;
    const int n0 = blockIdx.x * BN;
    const int lm = tid >> 1;              // 0..127 (row within tile)
    const int lk = (tid & 1) * 4;         // 0 or 4 (k quad)
    const int ttx = tid & 15;             // 0..15
    const int tty = tid >> 4;             // 0..15

    const float* ap = A  + (size_t)(m0 + lm) * BHd + lk;
    const float* bp = Bm + (size_t)(n0 + lm) * BHd + lk;

    u64 acc[8][4];
    zero_acc(acc);

    // Prologue: fill buffer 0
    {
        float4 av = *(const float4*)(ap);
        float4 bv = *(const float4*)(bp);
        As[0][lk + 0][lm] = av.x; As[0][lk + 1][lm] = av.y;
        As[0][lk + 2][lm] = av.z; As[0][lk + 3][lm] = av.w;
        Bs[0][lk + 0][lm] = bv.x; Bs[0][lk + 1][lm] = bv.y;
        Bs[0][lk + 2][lm] = bv.z; Bs[0][lk + 3][lm] = bv.w;
    }
    __syncthreads();

    int buf = 0;
    for (int k0 = 0; k0 < Hd; k0 += BK) {
        float4 av, bv;
        const bool has_next = (k0 + BK < Hd);
        if (has_next) {
            av = *(const float4*)(ap + k0 + BK);
            bv = *(const float4*)(bp + k0 + BK);
        }
        micro_fma(As[buf], Bs[buf], tty, ttx, acc);
        if (has_next) {
            const int nb = buf ^ 1;
            As[nb][lk + 0][lm] = av.x; As[nb][lk + 1][lm] = av.y;
            As[nb][lk + 2][lm] = av.z; As[nb][lk + 3][lm] = av.w;
            Bs[nb][lk + 0][lm] = bv.x; Bs[nb][lk + 1][lm] = bv.y;
            Bs[nb][lk + 2][lm] = bv.z; Bs[nb][lk + 3][lm] = bv.w;
        }
        __syncthreads();
        buf ^= 1;
    }

#pragma unroll
    for (int i = 0; i < 8; i++) {
        const int row = m0 + tty * 8 + i;
        store_row(C + (size_t)row * Sd + n0 + ttx * 8, acc[i]);
    }
}

// ---------------------------------------------------------------------------
// K2: fused mask + softmax over s (rows of length 2048), in place.
// ---------------------------------------------------------------------------
__global__ __launch_bounds__(256) void softmax_kernel(
    float* __restrict__ attn, const unsigned char* __restrict__ mask)
{
    __shared__ float redmax[8];
    __shared__ float redsum[8];

    const int row = blockIdx.x;                         // b*T + t
    float* p = attn + (size_t)row * Sd;
    const unsigned char* mp = mask + (size_t)row * Sd;
    const int tid = threadIdx.x;
    const int base = tid * 8;

    float4 v0 = *(const float4*)(p + base);
    float4 v1 = *(const float4*)(p + base + 4);
    unsigned long long mb = *(const unsigned long long*)(mp + base);
    float v[8] = {v0.x, v0.y, v0.z, v0.w, v1.x, v1.y, v1.z, v1.w};
#pragma unroll
    for (int i = 0; i < 8; i++)
        if ((mb >> (8 * i)) & 0xffULL) v[i] = -INFINITY;

    float mx = v[0];
#pragma unroll
    for (int i = 1; i < 8; i++) mx = fmaxf(mx, v[i]);
#pragma unroll
    for (int o = 16; o > 0; o >>= 1)
        mx = fmaxf(mx, __shfl_xor_sync(0xffffffffu, mx, o));
    const int wid = tid >> 5, lane = tid & 31;
    if (lane == 0) redmax[wid] = mx;
    __syncthreads();
    float rmax = redmax[0];
#pragma unroll
    for (int i = 1; i < 8; i++) rmax = fmaxf(rmax, redmax[i]);

    float s = 0.0f;
#pragma unroll
    for (int i = 0; i < 8; i++) {
        v[i] = __expf(v[i] - rmax);
        s += v[i];
    }
#pragma unroll
    for (int o = 16; o > 0; o >>= 1)
        s += __shfl_xor_sync(0xffffffffu, s, o);
    if (lane == 0) redsum[wid] = s;
    __syncthreads();
    float total = 0.0f;
#pragma unroll
    for (int i = 0; i < 8; i++) total += redsum[i];

    const float inv = 1.0f / total;
#pragma unroll
    for (int i = 0; i < 8; i++) v[i] *= inv;
    *(float4*)(p + base)     = make_float4(v[0], v[1], v[2], v[3]);
    *(float4*)(p + base + 4) = make_float4(v[4], v[5], v[6], v[7]);
}

// ---------------------------------------------------------------------------
// K3: context[t,b,h] = sum_s attn[b,t,s] * memory[s,b,h]   (NN GEMM per batch)
// ---------------------------------------------------------------------------
__global__ __launch_bounds__(256) void gemm_ctx(
    const float* __restrict__ attn, const float* __restrict__ mem)
{
    const int b = blockIdx.z;
    const float* A = attn + (size_t)b * Td * Sd;   // row t, stride Sd, k=s contiguous

    __shared__ float As[2][BK][BM];
    __shared__ float Bs[2][BK][BN];

    const int tid = threadIdx.x;
    const int m0 = blockIdx.y * BM;
    const int n0 = blockIdx.x * BN;
    const int lm = tid >> 1;
    const int lk = (tid & 1) * 4;
    const int lkb = tid >> 5;             // 0..7 (k row for B load)
    const int lnb = (tid & 31) * 4;       // 0..124 (n quad for B load)
    const int ttx = tid & 15;
    const int tty = tid >> 4;

    const float* ap = A + (size_t)(m0 + lm) * Sd + lk;
    const float* bp = mem + b * Hd + n0 + lnb + (size_t)lkb * BHd;

    u64 acc[8][4];
    zero_acc(acc);

    {
        float4 av = *(const float4*)(ap);
        float4 bv = *(const float4*)(bp);
        As[0][lk + 0][lm] = av.x; As[0][lk + 1][lm] = av.y;
        As[0][lk + 2][lm] = av.z; As[0][lk + 3][lm] = av.w;
        *(float4*)&Bs[0][lkb][lnb] = bv;
    }
    __syncthreads();

    int buf = 0;
    for (int k0 = 0; k0 < Sd; k0 += BK) {
        float4 av, bv;
        const bool has_next = (k0 + BK < Sd);
        if (has_next) {
            av = *(const float4*)(ap + k0 + BK);
            bv = *(const float4*)(bp + (size_t)(k0 + BK) * BHd);
        }
        micro_fma(As[buf], Bs[buf], tty, ttx, acc);
        if (has_next) {
            const int nb = buf ^ 1;
            As[nb][lk + 0][lm] = av.x; As[nb][lk + 1][lm] = av.y;
            As[nb][lk + 2][lm] = av.z; As[nb][lk + 3][lm] = av.w;
            *(float4*)&Bs[nb][lkb][lnb] = bv;
        }
        __syncthreads();
        buf ^= 1;
    }

#pragma unroll
    for (int i = 0; i < 8; i++) {
        const int row = m0 + tty * 8 + i;   // t
        store_row(g_ctx + (size_t)row * BHd + b * Hd + n0 + ttx * 8, acc[i]);
    }
}

// ---------------------------------------------------------------------------
// K4: out[r,h] = tanh( b[h] + sum_d [ctx | output][r,d] * W[h,d] )   (NT GEMM)
// r = t*B + b over 16384 rows, K = 2048 split into two 1024 halves.
// ---------------------------------------------------------------------------
__global__ __launch_bounds__(256) void gemm_linear(
    const float* __restrict__ outp, const float* __restrict__ W,
    const float* __restrict__ bias, float* __restrict__ out)
{
    __shared__ float As[2][BK][BM];
    __shared__ float Bs[2][BK][BN];

    const int tid = threadIdx.x;
    const int m0 = blockIdx.y * BM;
    const int n0 = blockIdx.x * BN;
    const int lm = tid >> 1;
    const int lk = (tid & 1) * 4;
    const int ttx = tid & 15;
    const int tty = tid >> 4;

    const float* actx = g_ctx + (size_t)(m0 + lm) * Hd + lk;
    const float* aout = outp  + (size_t)(m0 + lm) * Hd + lk;
    const float* wp   = W + (size_t)(n0 + lm) * (2 * Hd) + lk;

    u64 acc[8][4];
    zero_acc(acc);

    {
        float4 av = *(const float4*)(actx);
        float4 wv = *(const float4*)(wp);
        As[0][lk + 0][lm] = av.x; As[0][lk + 1][lm] = av.y;
        As[0][lk + 2][lm] = av.z; As[0][lk + 3][lm] = av.w;
        Bs[0][lk + 0][lm] = wv.x; Bs[0][lk + 1][lm] = wv.y;
        Bs[0][lk + 2][lm] = wv.z; Bs[0][lk + 3][lm] = wv.w;
    }
    __syncthreads();

    int buf = 0;
    for (int k0 = 0; k0 < 2 * Hd; k0 += BK) {
        float4 av, wv;
        const bool has_next = (k0 + BK < 2 * Hd);
        if (has_next) {
            const int kn = k0 + BK;
            av = (kn < Hd) ? *(const float4*)(actx + kn)
                           : *(const float4*)(aout + (kn - Hd));
            wv = *(const float4*)(wp + kn);
        }
        micro_fma(As[buf], Bs[buf], tty, ttx, acc);
        if (has_next) {
            const int nb = buf ^ 1;
            As[nb][lk + 0][lm] = av.x; As[nb][lk + 1][lm] = av.y;
            As[nb][lk + 2][lm] = av.z; As[nb][lk + 3][lm] = av.w;
            Bs[nb][lk + 0][lm] = wv.x; Bs[nb][lk + 1][lm] = wv.y;
            Bs[nb][lk + 2][lm] = wv.z; Bs[nb][lk + 3][lm] = wv.w;
        }
        __syncthreads();
        buf ^= 1;
    }

    float bb[8];
#pragma unroll
    for (int j = 0; j < 8; j++) bb[j] = bias[n0 + ttx * 8 + j];

#pragma unroll
    for (int i = 0; i < 8; i++) {
        const int row = m0 + tty * 8 + i;
        float* cp = out + (size_t)row * Hd + n0 + ttx * 8;
        float r[8];
        unpack2(acc[i][0], r[0], r[1]); unpack2(acc[i][1], r[2], r[3]);
        unpack2(acc[i][2], r[4], r[5]); unpack2(acc[i][3], r[6], r[7]);
#pragma unroll
        for (int j = 0; j < 8; j++) r[j] = tanhf(r[j] + bb[j]);
        *(float4*)(cp)     = make_float4(r[0], r[1], r[2], r[3]);
        *(float4*)(cp + 4) = make_float4(r[4], r[5], r[6], r[7]);
    }
}

// ---------------------------------------------------------------------------
extern "C" void kernel_launch(void* const* d_in, const int* in_sizes, int n_in,
                              void* d_out, int out_size)
{
    const float* outp = (const float*)d_in[0];           // (T,B,H)
    const float* mem  = (const float*)d_in[1];           // (S,B,H)
    const unsigned char* mask = (const unsigned char*)d_in[2]; // (B,T,S) bool
    const float* W    = (const float*)d_in[3];           // (H, 2H)
    const float* bias = (const float*)d_in[4];           // (H,)

    float* out  = (float*)d_out;                         // (T,B,H)
    float* attn = out + (size_t)Td * Bd * Hd;            // (B,T,S)

    dim3 blk(256);
    gemm_scores<<<dim3(Sd / BN, Td / BM, Bd), blk>>>(outp, mem, attn);
    softmax_kernel<<<Bd * Td, 256>>>(attn, mask);
    gemm_ctx<<<dim3(Hd / BN, Td / BM, Bd), blk>>>(attn, mem);
    gemm_linear<<<dim3(Hd / BN, (Td * Bd) / BM), blk>>>(outp, W, bias, out);
}

// round 11
// speedup vs baseline: 2.4428x; 2.4428x over previous
#include <cuda_runtime.h>
#include <cuda_bf16.h>
#include <math.h>
#include <stdint.h>

// Problem dims
#define Td 1024
#define Bd 16
#define Hd 1024
#define Sd 2048
#define BHd (Bd*Hd)   // 16384

typedef __nv_bfloat16 bf16;

// ---------------------------------------------------------------------------
// Device-global scratch (no allocs allowed)
// ---------------------------------------------------------------------------
__device__ float g_ctx[(size_t)Td * Bd * Hd];
__device__ bf16 g_out_hi[(size_t)Td * Bd * Hd], g_out_lo[(size_t)Td * Bd * Hd];
__device__ bf16 g_mem_hi[(size_t)Sd * Bd * Hd], g_mem_lo[(size_t)Sd * Bd * Hd];
__device__ bf16 g_memT_hi[(size_t)Bd * Hd * Sd], g_memT_lo[(size_t)Bd * Hd * Sd]; // (B,H,S)
__device__ bf16 g_W_hi[(size_t)Hd * 2 * Hd], g_W_lo[(size_t)Hd * 2 * Hd];
__device__ bf16 g_P_hi[(size_t)Bd * Td * Sd], g_P_lo[(size_t)Bd * Td * Sd];
__device__ bf16 g_ctx_hi[(size_t)Td * Bd * Hd], g_ctx_lo[(size_t)Td * Bd * Hd];

// ---------------------------------------------------------------------------
// Helpers
// ---------------------------------------------------------------------------
__device__ __forceinline__ uint32_t s2u(const void* p) {
    uint32_t a;
    asm("{ .reg .u64 t; cvta.to.shared.u64 t, %1; cvt.u32.u64 %0, t; }" : "=r"(a) : "l"(p));
    return a;
}
__device__ __forceinline__ void cpa16(uint32_t s, const void* g) {
    asm volatile("cp.async.cg.shared.global [%0], [%1], 16;" :: "r"(s), "l"(g));
}
__device__ __forceinline__ void cpa_commit() {
    asm volatile("cp.async.commit_group;" ::: "memory");
}
__device__ __forceinline__ void cpa_wait0() {
    asm volatile("cp.async.wait_group 0;" ::: "memory");
}
__device__ __forceinline__ void mma16816(float* c, const uint32_t* a, const uint32_t* b) {
    asm volatile(
        "mma.sync.aligned.m16n8k16.row.col.f32.bf16.bf16.f32 "
        "{%0,%1,%2,%3}, {%4,%5,%6,%7}, {%8,%9}, {%0,%1,%2,%3};"
        : "+f"(c[0]), "+f"(c[1]), "+f"(c[2]), "+f"(c[3])
        : "r"(a[0]), "r"(a[1]), "r"(a[2]), "r"(a[3]), "r"(b[0]), "r"(b[1]));
}

// Tile geometry: 128x128 CTA tile, BK=32 bf16. Rows padded to 80B (40 bf16).
#define TROW 40
#define TILE_B (128 * TROW * 2)      // 10240 B per tile
#define STAGE_B (4 * TILE_B)         // Ah, Al, Bh, Bl
#define SMEM_B (2 * STAGE_B)         // double buffer: 81920 B

// Issue cp.async for one stage. Expressions use `row` (tile row 0..127) and
// `kk0` (k element offset of the 8-element segment within the full K dim).
#define LOAD_STAGE(st, kc, AHI, ALO, BHI, BLO)                               \
    {                                                                        \
        const int c_ = (kc);                                                 \
        _Pragma("unroll")                                                    \
        for (int j_ = 0; j_ < 2; j_++) {                                     \
            const int s_ = j_ * 256 + tid;                                   \
            const int row = s_ >> 2, off_ = s_ & 3;                          \
            const int kk0 = c_ * 32 + off_ * 8;                              \
            const uint32_t so_ = sbase + (st) * STAGE_B + row * 80 + off_ * 16; \
            cpa16(so_,              (const void*)(AHI));                     \
            cpa16(so_ + TILE_B,     (const void*)(ALO));                     \
            cpa16(so_ + 2 * TILE_B, (const void*)(BHI));                     \
            cpa16(so_ + 3 * TILE_B, (const void*)(BLO));                     \
        }                                                                    \
    }

// ---------------------------------------------------------------------------
// Compute one BK=32 stage: 2 k16-steps, 3 split passes (hh, hl, lh).
// Warp tile 64x32: 4 m-tiles (16) x 4 n-tiles (8).
// ---------------------------------------------------------------------------
__device__ __forceinline__ void compute_stage(
    char* sm, int st, int wm, int wn, int lane, float acc[4][4][4])
{
    bf16 (*Ah)[TROW] = (bf16(*)[TROW])(sm + st * STAGE_B);
    bf16 (*Al)[TROW] = (bf16(*)[TROW])(sm + st * STAGE_B + TILE_B);
    bf16 (*Bh)[TROW] = (bf16(*)[TROW])(sm + st * STAGE_B + 2 * TILE_B);
    bf16 (*Bl)[TROW] = (bf16(*)[TROW])(sm + st * STAGE_B + 3 * TILE_B);
    const int g = lane >> 2, i2 = (lane & 3) * 2;
#pragma unroll
    for (int ks = 0; ks < 2; ks++) {
        const int ca = ks * 16 + i2;
        uint32_t bhf[4][2], blf[4][2];
#pragma unroll
        for (int nt = 0; nt < 4; nt++) {
            const int rb = wn * 32 + nt * 8 + g;
            bhf[nt][0] = *(const uint32_t*)&Bh[rb][ca];
            bhf[nt][1] = *(const uint32_t*)&Bh[rb][ca + 8];
            blf[nt][0] = *(const uint32_t*)&Bl[rb][ca];
            blf[nt][1] = *(const uint32_t*)&Bl[rb][ca + 8];
        }
#pragma unroll
        for (int mt = 0; mt < 4; mt++) {
            const int ra = wm * 64 + mt * 16 + g;
            uint32_t ahf[4] = {
                *(const uint32_t*)&Ah[ra][ca],     *(const uint32_t*)&Ah[ra + 8][ca],
                *(const uint32_t*)&Ah[ra][ca + 8], *(const uint32_t*)&Ah[ra + 8][ca + 8]};
            uint32_t alf[4] = {
                *(const uint32_t*)&Al[ra][ca],     *(const uint32_t*)&Al[ra + 8][ca],
                *(const uint32_t*)&Al[ra][ca + 8], *(const uint32_t*)&Al[ra + 8][ca + 8]};
#pragma unroll
            for (int nt = 0; nt < 4; nt++) {
                mma16816(acc[mt][nt], ahf, bhf[nt]);
                mma16816(acc[mt][nt], ahf, blf[nt]);
                mma16816(acc[mt][nt], alf, bhf[nt]);
            }
        }
    }
}

#define MMA_PRE()                                                             \
    extern __shared__ char sm[];                                              \
    const uint32_t sbase = s2u(sm);                                           \
    const int tid = threadIdx.x, wid = tid >> 5, lane = tid & 31;             \
    const int wm = wid >> 2, wn = wid & 3;                                    \
    const int g = lane >> 2, i2 = (lane & 3) * 2;                             \
    float acc[4][4][4];                                                       \
    _Pragma("unroll")                                                         \
    for (int a_ = 0; a_ < 4; a_++)                                            \
        _Pragma("unroll")                                                     \
        for (int b_ = 0; b_ < 4; b_++)                                        \
            _Pragma("unroll")                                                 \
            for (int c2_ = 0; c2_ < 4; c2_++) acc[a_][b_][c2_] = 0.0f;

// ---------------------------------------------------------------------------
// K1: scores[b,t,s] = sum_h out*mem  (K=1024, 32 chunks)
// ---------------------------------------------------------------------------
__global__ __launch_bounds__(256) void mma_scores(float* __restrict__ attn)
{
    const int b = blockIdx.z, m0 = blockIdx.y * 128, n0 = blockIdx.x * 128;
    MMA_PRE()
    LOAD_STAGE(0, 0,
        g_out_hi + ((size_t)(m0 + row) * BHd + b * Hd + kk0),
        g_out_lo + ((size_t)(m0 + row) * BHd + b * Hd + kk0),
        g_mem_hi + ((size_t)(n0 + row) * BHd + b * Hd + kk0),
        g_mem_lo + ((size_t)(n0 + row) * BHd + b * Hd + kk0))
    cpa_commit();
    int buf = 0;
    for (int c = 0; c < 32; c++) {
        cpa_wait0();
        __syncthreads();
        if (c + 1 < 32) {
            LOAD_STAGE(buf ^ 1, c + 1,
                g_out_hi + ((size_t)(m0 + row) * BHd + b * Hd + kk0),
                g_out_lo + ((size_t)(m0 + row) * BHd + b * Hd + kk0),
                g_mem_hi + ((size_t)(n0 + row) * BHd + b * Hd + kk0),
                g_mem_lo + ((size_t)(n0 + row) * BHd + b * Hd + kk0))
        }
        cpa_commit();
        compute_stage(sm, buf, wm, wn, lane, acc);
        buf ^= 1;
    }
#pragma unroll
    for (int mt = 0; mt < 4; mt++)
#pragma unroll
        for (int nt = 0; nt < 4; nt++) {
            const int r0 = m0 + wm * 64 + mt * 16 + g;
            const int cc = n0 + wn * 32 + nt * 8 + i2;
            float* p = attn + (size_t)b * Td * Sd + (size_t)r0 * Sd + cc;
            *(float2*)p = make_float2(acc[mt][nt][0], acc[mt][nt][1]);
            *(float2*)(p + 8 * Sd) = make_float2(acc[mt][nt][2], acc[mt][nt][3]);
        }
}

// ---------------------------------------------------------------------------
// K3: ctx[t,b,h] = sum_s P*mem (B from memT; K=2048, 64 chunks)
// ---------------------------------------------------------------------------
__global__ __launch_bounds__(256) void mma_ctx()
{
    const int b = blockIdx.z, m0 = blockIdx.y * 128, n0 = blockIdx.x * 128;
    MMA_PRE()
    LOAD_STAGE(0, 0,
        g_P_hi + ((size_t)b * Td * Sd + (size_t)(m0 + row) * Sd + kk0),
        g_P_lo + ((size_t)b * Td * Sd + (size_t)(m0 + row) * Sd + kk0),
        g_memT_hi + ((size_t)b * Hd * Sd + (size_t)(n0 + row) * Sd + kk0),
        g_memT_lo + ((size_t)b * Hd * Sd + (size_t)(n0 + row) * Sd + kk0))
    cpa_commit();
    int buf = 0;
    for (int c = 0; c < 64; c++) {
        cpa_wait0();
        __syncthreads();
        if (c + 1 < 64) {
            LOAD_STAGE(buf ^ 1, c + 1,
                g_P_hi + ((size_t)b * Td * Sd + (size_t)(m0 + row) * Sd + kk0),
                g_P_lo + ((size_t)b * Td * Sd + (size_t)(m0 + row) * Sd + kk0),
                g_memT_hi + ((size_t)b * Hd * Sd + (size_t)(n0 + row) * Sd + kk0),
                g_memT_lo + ((size_t)b * Hd * Sd + (size_t)(n0 + row) * Sd + kk0))
        }
        cpa_commit();
        compute_stage(sm, buf, wm, wn, lane, acc);
        buf ^= 1;
    }
#pragma unroll
    for (int mt = 0; mt < 4; mt++)
#pragma unroll
        for (int nt = 0; nt < 4; nt++) {
            const int r0 = m0 + wm * 64 + mt * 16 + g;   // t
            const int cc = n0 + wn * 32 + nt * 8 + i2;   // h
            float* p = g_ctx + (size_t)r0 * BHd + b * Hd + cc;
            *(float2*)p = make_float2(acc[mt][nt][0], acc[mt][nt][1]);
            *(float2*)(p + 8 * BHd) = make_float2(acc[mt][nt][2], acc[mt][nt][3]);
        }
}

// ---------------------------------------------------------------------------
// K4: out[r,n] = tanh(bias + sum_d [ctx|out]*W)  (K=2048, 64 chunks)
// ---------------------------------------------------------------------------
__global__ __launch_bounds__(256) void mma_linear(
    const float* __restrict__ bias, float* __restrict__ out)
{
    const int m0 = blockIdx.y * 128, n0 = blockIdx.x * 128;
    MMA_PRE()
    LOAD_STAGE(0, 0,
        ((kk0 < Hd) ? (g_ctx_hi + ((size_t)(m0 + row) * Hd + kk0))
                    : (g_out_hi + ((size_t)(m0 + row) * Hd + (kk0 - Hd)))),
        ((kk0 < Hd) ? (g_ctx_lo + ((size_t)(m0 + row) * Hd + kk0))
                    : (g_out_lo + ((size_t)(m0 + row) * Hd + (kk0 - Hd)))),
        g_W_hi + ((size_t)(n0 + row) * (2 * Hd) + kk0),
        g_W_lo + ((size_t)(n0 + row) * (2 * Hd) + kk0))
    cpa_commit();
    int buf = 0;
    for (int c = 0; c < 64; c++) {
        cpa_wait0();
        __syncthreads();
        if (c + 1 < 64) {
            LOAD_STAGE(buf ^ 1, c + 1,
                ((kk0 < Hd) ? (g_ctx_hi + ((size_t)(m0 + row) * Hd + kk0))
                            : (g_out_hi + ((size_t)(m0 + row) * Hd + (kk0 - Hd)))),
                ((kk0 < Hd) ? (g_ctx_lo + ((size_t)(m0 + row) * Hd + kk0))
                            : (g_out_lo + ((size_t)(m0 + row) * Hd + (kk0 - Hd)))),
                g_W_hi + ((size_t)(n0 + row) * (2 * Hd) + kk0),
                g_W_lo + ((size_t)(n0 + row) * (2 * Hd) + kk0))
        }
        cpa_commit();
        compute_stage(sm, buf, wm, wn, lane, acc);
        buf ^= 1;
    }
#pragma unroll
    for (int mt = 0; mt < 4; mt++)
#pragma unroll
        for (int nt = 0; nt < 4; nt++) {
            const int r0 = m0 + wm * 64 + mt * 16 + g;
            const int cc = n0 + wn * 32 + nt * 8 + i2;
            const float b0 = bias[cc], b1 = bias[cc + 1];
            float* p = out + (size_t)r0 * Hd + cc;
            *(float2*)p = make_float2(tanhf(acc[mt][nt][0] + b0), tanhf(acc[mt][nt][1] + b1));
            *(float2*)(p + 8 * Hd) =
                make_float2(tanhf(acc[mt][nt][2] + b0), tanhf(acc[mt][nt][3] + b1));
        }
}

// ---------------------------------------------------------------------------
// bf16 split conversion: hi = bf16(x); lo = bf16(x - hi). 4 elems/thread.
// ---------------------------------------------------------------------------
__global__ void split4(const float* __restrict__ src, bf16* __restrict__ hi,
                       bf16* __restrict__ lo, size_t n4)
{
    size_t i = (size_t)blockIdx.x * blockDim.x + threadIdx.x;
    if (i >= n4) return;
    float4 v = ((const float4*)src)[i];
    __nv_bfloat162 h0, h1, l0, l1;
    h0.x = __float2bfloat16(v.x); h0.y = __float2bfloat16(v.y);
    h1.x = __float2bfloat16(v.z); h1.y = __float2bfloat16(v.w);
    l0.x = __float2bfloat16(v.x - __bfloat162float(h0.x));
    l0.y = __float2bfloat16(v.y - __bfloat162float(h0.y));
    l1.x = __float2bfloat16(v.z - __bfloat162float(h1.x));
    l1.y = __float2bfloat16(v.w - __bfloat162float(h1.y));
    ((__nv_bfloat162*)hi)[2 * i] = h0; ((__nv_bfloat162*)hi)[2 * i + 1] = h1;
    ((__nv_bfloat162*)lo)[2 * i] = l0; ((__nv_bfloat162*)lo)[2 * i + 1] = l1;
}

// ---------------------------------------------------------------------------
// Transposed split of memory: memT[b][h][s] = split(memory[s][b][h])
// ---------------------------------------------------------------------------
__global__ __launch_bounds__(1024) void transpose_split(const float* __restrict__ mem)
{
    __shared__ float t[32][33];
    const int b = blockIdx.z;
    const int s0 = blockIdx.x * 32, h0 = blockIdx.y * 32;
    const int tx = threadIdx.x, ty = threadIdx.y;
    t[ty][tx] = mem[(size_t)(s0 + ty) * BHd + b * Hd + h0 + tx];
    __syncthreads();
    const float v = t[tx][ty];
    const size_t o = (size_t)b * Hd * Sd + (size_t)(h0 + ty) * Sd + s0 + tx;
    bf16 h = __float2bfloat16(v);
    g_memT_hi[o] = h;
    g_memT_lo[o] = __float2bfloat16(v - __bfloat162float(h));
}

// ---------------------------------------------------------------------------
// K2: fused mask + softmax over s (rows of length 2048), in place
// ---------------------------------------------------------------------------
__global__ __launch_bounds__(256) void softmax_kernel(
    float* __restrict__ attn, const unsigned char* __restrict__ mask)
{
    __shared__ float redmax[8];
    __shared__ float redsum[8];

    const int row = blockIdx.x;
    float* p = attn + (size_t)row * Sd;
    const unsigned char* mp = mask + (size_t)row * Sd;
    const int tid = threadIdx.x;
    const int base = tid * 8;

    float4 v0 = *(const float4*)(p + base);
    float4 v1 = *(const float4*)(p + base + 4);
    unsigned long long mb = *(const unsigned long long*)(mp + base);
    float v[8] = {v0.x, v0.y, v0.z, v0.w, v1.x, v1.y, v1.z, v1.w};
#pragma unroll
    for (int i = 0; i < 8; i++)
        if ((mb >> (8 * i)) & 0xffULL) v[i] = -INFINITY;

    float mx = v[0];
#pragma unroll
    for (int i = 1; i < 8; i++) mx = fmaxf(mx, v[i]);
#pragma unroll
    for (int o = 16; o > 0; o >>= 1)
        mx = fmaxf(mx, __shfl_xor_sync(0xffffffffu, mx, o));
    const int wid = tid >> 5, lane = tid & 31;
    if (lane == 0) redmax[wid] = mx;
    __syncthreads();
    float rmax = redmax[0];
#pragma unroll
    for (int i = 1; i < 8; i++) rmax = fmaxf(rmax, redmax[i]);

    float s = 0.0f;
#pragma unroll
    for (int i = 0; i < 8; i++) {
        v[i] = __expf(v[i] - rmax);
        s += v[i];
    }
#pragma unroll
    for (int o = 16; o > 0; o >>= 1)
        s += __shfl_xor_sync(0xffffffffu, s, o);
    if (lane == 0) redsum[wid] = s;
    __syncthreads();
    float total = 0.0f;
#pragma unroll
    for (int i = 0; i < 8; i++) total += redsum[i];

    const float inv = 1.0f / total;
#pragma unroll
    for (int i = 0; i < 8; i++) v[i] *= inv;
    *(float4*)(p + base)     = make_float4(v[0], v[1], v[2], v[3]);
    *(float4*)(p + base + 4) = make_float4(v[4], v[5], v[6], v[7]);
}

// ---------------------------------------------------------------------------
extern "C" void kernel_launch(void* const* d_in, const int* in_sizes, int n_in,
                              void* d_out, int out_size)
{
    const float* outp = (const float*)d_in[0];                 // (T,B,H)
    const float* mem  = (const float*)d_in[1];                 // (S,B,H)
    const unsigned char* mask = (const unsigned char*)d_in[2]; // (B,T,S)
    const float* W    = (const float*)d_in[3];                 // (H,2H)
    const float* bias = (const float*)d_in[4];                 // (H,)

    float* out  = (float*)d_out;                               // (T,B,H)
    float* attn = out + (size_t)Td * Bd * Hd;                  // (B,T,S)

    void *p_oh, *p_ol, *p_mh, *p_ml, *p_wh, *p_wl, *p_ph, *p_pl, *p_ch, *p_cl, *p_cx;
    cudaGetSymbolAddress(&p_oh, g_out_hi);  cudaGetSymbolAddress(&p_ol, g_out_lo);
    cudaGetSymbolAddress(&p_mh, g_mem_hi);  cudaGetSymbolAddress(&p_ml, g_mem_lo);
    cudaGetSymbolAddress(&p_wh, g_W_hi);    cudaGetSymbolAddress(&p_wl, g_W_lo);
    cudaGetSymbolAddress(&p_ph, g_P_hi);    cudaGetSymbolAddress(&p_pl, g_P_lo);
    cudaGetSymbolAddress(&p_ch, g_ctx_hi);  cudaGetSymbolAddress(&p_cl, g_ctx_lo);
    cudaGetSymbolAddress(&p_cx, g_ctx);

    cudaFuncSetAttribute(mma_scores, cudaFuncAttributeMaxDynamicSharedMemorySize, SMEM_B);
    cudaFuncSetAttribute(mma_ctx,    cudaFuncAttributeMaxDynamicSharedMemorySize, SMEM_B);
    cudaFuncSetAttribute(mma_linear, cudaFuncAttributeMaxDynamicSharedMemorySize, SMEM_B);

    const size_t nTBH = (size_t)Td * Bd * Hd;
    const size_t nSBH = (size_t)Sd * Bd * Hd;
    const size_t nBTS = (size_t)Bd * Td * Sd;
    const size_t nW   = (size_t)Hd * 2 * Hd;

    split4<<<(unsigned)((nTBH / 4 + 255) / 256), 256>>>(outp, (bf16*)p_oh, (bf16*)p_ol, nTBH / 4);
    split4<<<(unsigned)((nSBH / 4 + 255) / 256), 256>>>(mem, (bf16*)p_mh, (bf16*)p_ml, nSBH / 4);
    transpose_split<<<dim3(Sd / 32, Hd / 32, Bd), dim3(32, 32)>>>(mem);
    split4<<<(unsigned)((nW / 4 + 255) / 256), 256>>>(W, (bf16*)p_wh, (bf16*)p_wl, nW / 4);

    mma_scores<<<dim3(Sd / 128, Td / 128, Bd), 256, SMEM_B>>>(attn);
    softmax_kernel<<<Bd * Td, 256>>>(attn, mask);
    split4<<<(unsigned)((nBTS / 4 + 255) / 256), 256>>>(attn, (bf16*)p_ph, (bf16*)p_pl, nBTS / 4);
    mma_ctx<<<dim3(Hd / 128, Td / 128, Bd), 256, SMEM_B>>>();
    split4<<<(unsigned)((nTBH / 4 + 255) / 256), 256>>>((const float*)p_cx, (bf16*)p_ch, (bf16*)p_cl, nTBH / 4);
    mma_linear<<<dim3(Hd / 128, (Td * Bd) / 128), 256, SMEM_B>>>(bias, out);
}

// round 13
// speedup vs baseline: 2.5496x; 1.0437x over previous
#include <cuda_runtime.h>
#include <cuda_bf16.h>
#include <math.h>
#include <stdint.h>

// Problem dims
#define Td 1024
#define Bd 16
#define Hd 1024
#define Sd 2048
#define BHd (Bd*Hd)   // 16384

typedef __nv_bfloat16 bf16;

// ---------------------------------------------------------------------------
// Device-global scratch (no allocs allowed)
// ---------------------------------------------------------------------------
__device__ bf16 g_out_hi[(size_t)Td * Bd * Hd], g_out_lo[(size_t)Td * Bd * Hd];
__device__ bf16 g_mem_hi[(size_t)Sd * Bd * Hd], g_mem_lo[(size_t)Sd * Bd * Hd];
__device__ bf16 g_memT_hi[(size_t)Bd * Hd * Sd], g_memT_lo[(size_t)Bd * Hd * Sd]; // (B,H,S)
__device__ bf16 g_W_hi[(size_t)Hd * 2 * Hd], g_W_lo[(size_t)Hd * 2 * Hd];
__device__ bf16 g_P_hi[(size_t)Bd * Td * Sd], g_P_lo[(size_t)Bd * Td * Sd];
__device__ bf16 g_ctx_hi[(size_t)Td * Bd * Hd], g_ctx_lo[(size_t)Td * Bd * Hd];

// ---------------------------------------------------------------------------
// Helpers
// ---------------------------------------------------------------------------
__device__ __forceinline__ uint32_t s2u(const void* p) {
    uint32_t a;
    asm("{ .reg .u64 t; cvta.to.shared.u64 t, %1; cvt.u32.u64 %0, t; }" : "=r"(a) : "l"(p));
    return a;
}
__device__ __forceinline__ void cpa16(uint32_t s, const void* g) {
    asm volatile("cp.async.cg.shared.global [%0], [%1], 16;" :: "r"(s), "l"(g));
}
__device__ __forceinline__ void cpa_commit() {
    asm volatile("cp.async.commit_group;" ::: "memory");
}
__device__ __forceinline__ void cpa_wait0() {
    asm volatile("cp.async.wait_group 0;" ::: "memory");
}
__device__ __forceinline__ void mma16816(float* c, const uint32_t* a, const uint32_t* b) {
    asm volatile(
        "mma.sync.aligned.m16n8k16.row.col.f32.bf16.bf16.f32 "
        "{%0,%1,%2,%3}, {%4,%5,%6,%7}, {%8,%9}, {%0,%1,%2,%3};"
        : "+f"(c[0]), "+f"(c[1]), "+f"(c[2]), "+f"(c[3])
        : "r"(a[0]), "r"(a[1]), "r"(a[2]), "r"(a[3]), "r"(b[0]), "r"(b[1]));
}

// Tile geometry: 128x128 CTA tile, BK=32 bf16. Rows padded to 80B (40 bf16).
#define TROW 40
#define TILE_B (128 * TROW * 2)      // 10240 B per tile
#define STAGE_B (4 * TILE_B)         // Ah, Al, Bh, Bl
#define SMEM_B (2 * STAGE_B)         // double buffer: 81920 B

// Issue cp.async for one stage. Expressions use `row` (tile row 0..127) and
// `kk0` (k element offset of the 8-element segment within the full K dim).
#define LOAD_STAGE(st, kc, AHI, ALO, BHI, BLO)                               \
    {                                                                        \
        const int c_ = (kc);                                                 \
        _Pragma("unroll")                                                    \
        for (int j_ = 0; j_ < 2; j_++) {                                     \
            const int s_ = j_ * 256 + tid;                                   \
            const int row = s_ >> 2, off_ = s_ & 3;                          \
            const int kk0 = c_ * 32 + off_ * 8;                              \
            const uint32_t so_ = sbase + (st) * STAGE_B + row * 80 + off_ * 16; \
            cpa16(so_,              (const void*)(AHI));                     \
            cpa16(so_ + TILE_B,     (const void*)(ALO));                     \
            cpa16(so_ + 2 * TILE_B, (const void*)(BHI));                     \
            cpa16(so_ + 3 * TILE_B, (const void*)(BLO));                     \
        }                                                                    \
    }

// ---------------------------------------------------------------------------
// Compute one BK=32 stage: 2 k16-steps, 3 split passes (hh, hl, lh).
// Warp tile 64x32: 4 m-tiles (16) x 4 n-tiles (8).
// ---------------------------------------------------------------------------
__device__ __forceinline__ void compute_stage(
    char* sm, int st, int wm, int wn, int lane, float acc[4][4][4])
{
    bf16 (*Ah)[TROW] = (bf16(*)[TROW])(sm + st * STAGE_B);
    bf16 (*Al)[TROW] = (bf16(*)[TROW])(sm + st * STAGE_B + TILE_B);
    bf16 (*Bh)[TROW] = (bf16(*)[TROW])(sm + st * STAGE_B + 2 * TILE_B);
    bf16 (*Bl)[TROW] = (bf16(*)[TROW])(sm + st * STAGE_B + 3 * TILE_B);
    const int g = lane >> 2, i2 = (lane & 3) * 2;
#pragma unroll
    for (int ks = 0; ks < 2; ks++) {
        const int ca = ks * 16 + i2;
        uint32_t bhf[4][2], blf[4][2];
#pragma unroll
        for (int nt = 0; nt < 4; nt++) {
            const int rb = wn * 32 + nt * 8 + g;
            bhf[nt][0] = *(const uint32_t*)&Bh[rb][ca];
            bhf[nt][1] = *(const uint32_t*)&Bh[rb][ca + 8];
            blf[nt][0] = *(const uint32_t*)&Bl[rb][ca];
            blf[nt][1] = *(const uint32_t*)&Bl[rb][ca + 8];
        }
#pragma unroll
        for (int mt = 0; mt < 4; mt++) {
            const int ra = wm * 64 + mt * 16 + g;
            uint32_t ahf[4] = {
                *(const uint32_t*)&Ah[ra][ca],     *(const uint32_t*)&Ah[ra + 8][ca],
                *(const uint32_t*)&Ah[ra][ca + 8], *(const uint32_t*)&Ah[ra + 8][ca + 8]};
            uint32_t alf[4] = {
                *(const uint32_t*)&Al[ra][ca],     *(const uint32_t*)&Al[ra + 8][ca],
                *(const uint32_t*)&Al[ra][ca + 8], *(const uint32_t*)&Al[ra + 8][ca + 8]};
#pragma unroll
            for (int nt = 0; nt < 4; nt++) {
                mma16816(acc[mt][nt], ahf, bhf[nt]);
                mma16816(acc[mt][nt], ahf, blf[nt]);
                mma16816(acc[mt][nt], alf, bhf[nt]);
            }
        }
    }
}

#define MMA_PRE()                                                             \
    extern __shared__ char sm[];                                              \
    const uint32_t sbase = s2u(sm);                                           \
    const int tid = threadIdx.x, wid = tid >> 5, lane = tid & 31;             \
    const int wm = wid >> 2, wn = wid & 3;                                    \
    const int g = lane >> 2, i2 = (lane & 3) * 2;                             \
    float acc[4][4][4];                                                       \
    _Pragma("unroll")                                                         \
    for (int a_ = 0; a_ < 4; a_++)                                            \
        _Pragma("unroll")                                                     \
        for (int b_ = 0; b_ < 4; b_++)                                        \
            _Pragma("unroll")                                                 \
            for (int c2_ = 0; c2_ < 4; c2_++) acc[a_][b_][c2_] = 0.0f;

// ---------------------------------------------------------------------------
// K1: scores[b,t,s] = sum_h out*mem  (K=1024, 32 chunks)
// ---------------------------------------------------------------------------
__global__ __launch_bounds__(256) void mma_scores(float* __restrict__ attn)
{
    const int b = blockIdx.z, m0 = blockIdx.y * 128, n0 = blockIdx.x * 128;
    MMA_PRE()
    LOAD_STAGE(0, 0,
        g_out_hi + ((size_t)(m0 + row) * BHd + b * Hd + kk0),
        g_out_lo + ((size_t)(m0 + row) * BHd + b * Hd + kk0),
        g_mem_hi + ((size_t)(n0 + row) * BHd + b * Hd + kk0),
        g_mem_lo + ((size_t)(n0 + row) * BHd + b * Hd + kk0))
    cpa_commit();
    int buf = 0;
    for (int c = 0; c < 32; c++) {
        cpa_wait0();
        __syncthreads();
        if (c + 1 < 32) {
            LOAD_STAGE(buf ^ 1, c + 1,
                g_out_hi + ((size_t)(m0 + row) * BHd + b * Hd + kk0),
                g_out_lo + ((size_t)(m0 + row) * BHd + b * Hd + kk0),
                g_mem_hi + ((size_t)(n0 + row) * BHd + b * Hd + kk0),
                g_mem_lo + ((size_t)(n0 + row) * BHd + b * Hd + kk0))
        }
        cpa_commit();
        compute_stage(sm, buf, wm, wn, lane, acc);
        buf ^= 1;
    }
#pragma unroll
    for (int mt = 0; mt < 4; mt++)
#pragma unroll
        for (int nt = 0; nt < 4; nt++) {
            const int r0 = m0 + wm * 64 + mt * 16 + g;
            const int cc = n0 + wn * 32 + nt * 8 + i2;
            float* p = attn + (size_t)b * Td * Sd + (size_t)r0 * Sd + cc;
            *(float2*)p = make_float2(acc[mt][nt][0], acc[mt][nt][1]);
            *(float2*)(p + 8 * Sd) = make_float2(acc[mt][nt][2], acc[mt][nt][3]);
        }
}

// ---------------------------------------------------------------------------
// K3: ctx = P*mem; epilogue converts accumulators straight to bf16 hi/lo
// ---------------------------------------------------------------------------
__global__ __launch_bounds__(256) void mma_ctx()
{
    const int b = blockIdx.z, m0 = blockIdx.y * 128, n0 = blockIdx.x * 128;
    MMA_PRE()
    LOAD_STAGE(0, 0,
        g_P_hi + ((size_t)b * Td * Sd + (size_t)(m0 + row) * Sd + kk0),
        g_P_lo + ((size_t)b * Td * Sd + (size_t)(m0 + row) * Sd + kk0),
        g_memT_hi + ((size_t)b * Hd * Sd + (size_t)(n0 + row) * Sd + kk0),
        g_memT_lo + ((size_t)b * Hd * Sd + (size_t)(n0 + row) * Sd + kk0))
    cpa_commit();
    int buf = 0;
    for (int c = 0; c < 64; c++) {
        cpa_wait0();
        __syncthreads();
        if (c + 1 < 64) {
            LOAD_STAGE(buf ^ 1, c + 1,
                g_P_hi + ((size_t)b * Td * Sd + (size_t)(m0 + row) * Sd + kk0),
                g_P_lo + ((size_t)b * Td * Sd + (size_t)(m0 + row) * Sd + kk0),
                g_memT_hi + ((size_t)b * Hd * Sd + (size_t)(n0 + row) * Sd + kk0),
                g_memT_lo + ((size_t)b * Hd * Sd + (size_t)(n0 + row) * Sd + kk0))
        }
        cpa_commit();
        compute_stage(sm, buf, wm, wn, lane, acc);
        buf ^= 1;
    }
#pragma unroll
    for (int mt = 0; mt < 4; mt++)
#pragma unroll
        for (int nt = 0; nt < 4; nt++) {
            const int r0 = m0 + wm * 64 + mt * 16 + g;   // t
            const int cc = n0 + wn * 32 + nt * 8 + i2;   // h
            // split fp32 accumulators into bf16 hi/lo in-register
            float v0 = acc[mt][nt][0], v1 = acc[mt][nt][1];
            float v2 = acc[mt][nt][2], v3 = acc[mt][nt][3];
            bf16 h0 = __float2bfloat16(v0), h1 = __float2bfloat16(v1);
            bf16 h2 = __float2bfloat16(v2), h3 = __float2bfloat16(v3);
            const size_t o  = (size_t)r0 * BHd + b * Hd + cc;
            const size_t o8 = o + (size_t)8 * BHd;
            __nv_bfloat162 hp0; hp0.x = h0; hp0.y = h1;
            __nv_bfloat162 hp1; hp1.x = h2; hp1.y = h3;
            *(__nv_bfloat162*)(g_ctx_hi + o)  = hp0;
            *(__nv_bfloat162*)(g_ctx_hi + o8) = hp1;
            __nv_bfloat162 lp0, lp1;
            lp0.x = __float2bfloat16(v0 - __bfloat162float(h0));
            lp0.y = __float2bfloat16(v1 - __bfloat162float(h1));
            lp1.x = __float2bfloat16(v2 - __bfloat162float(h2));
            lp1.y = __float2bfloat16(v3 - __bfloat162float(h3));
            *(__nv_bfloat162*)(g_ctx_lo + o)  = lp0;
            *(__nv_bfloat162*)(g_ctx_lo + o8) = lp1;
        }
}

// ---------------------------------------------------------------------------
// K4: out[r,n] = tanh(bias + sum_d [ctx|out]*W)  (K=2048, 64 chunks)
// ---------------------------------------------------------------------------
__global__ __launch_bounds__(256) void mma_linear(
    const float* __restrict__ bias, float* __restrict__ out)
{
    const int m0 = blockIdx.y * 128, n0 = blockIdx.x * 128;
    MMA_PRE()
    LOAD_STAGE(0, 0,
        ((kk0 < Hd) ? (g_ctx_hi + ((size_t)(m0 + row) * Hd + kk0))
                    : (g_out_hi + ((size_t)(m0 + row) * Hd + (kk0 - Hd)))),
        ((kk0 < Hd) ? (g_ctx_lo + ((size_t)(m0 + row) * Hd + kk0))
                    : (g_out_lo + ((size_t)(m0 + row) * Hd + (kk0 - Hd)))),
        g_W_hi + ((size_t)(n0 + row) * (2 * Hd) + kk0),
        g_W_lo + ((size_t)(n0 + row) * (2 * Hd) + kk0))
    cpa_commit();
    int buf = 0;
    for (int c = 0; c < 64; c++) {
        cpa_wait0();
        __syncthreads();
        if (c + 1 < 64) {
            LOAD_STAGE(buf ^ 1, c + 1,
                ((kk0 < Hd) ? (g_ctx_hi + ((size_t)(m0 + row) * Hd + kk0))
                            : (g_out_hi + ((size_t)(m0 + row) * Hd + (kk0 - Hd)))),
                ((kk0 < Hd) ? (g_ctx_lo + ((size_t)(m0 + row) * Hd + kk0))
                            : (g_out_lo + ((size_t)(m0 + row) * Hd + (kk0 - Hd)))),
                g_W_hi + ((size_t)(n0 + row) * (2 * Hd) + kk0),
                g_W_lo + ((size_t)(n0 + row) * (2 * Hd) + kk0))
        }
        cpa_commit();
        compute_stage(sm, buf, wm, wn, lane, acc);
        buf ^= 1;
    }
#pragma unroll
    for (int mt = 0; mt < 4; mt++)
#pragma unroll
        for (int nt = 0; nt < 4; nt++) {
            const int r0 = m0 + wm * 64 + mt * 16 + g;
            const int cc = n0 + wn * 32 + nt * 8 + i2;
            const float b0 = bias[cc], b1 = bias[cc + 1];
            float* p = out + (size_t)r0 * Hd + cc;
            *(float2*)p = make_float2(tanhf(acc[mt][nt][0] + b0), tanhf(acc[mt][nt][1] + b1));
            *(float2*)(p + 8 * Hd) =
                make_float2(tanhf(acc[mt][nt][2] + b0), tanhf(acc[mt][nt][3] + b1));
        }
}

// ---------------------------------------------------------------------------
// split8: hi = bf16(x); lo = bf16(x - hi). 8 elems/thread, uint4 stores.
// ---------------------------------------------------------------------------
__global__ void split8(const float* __restrict__ src, bf16* __restrict__ hi,
                       bf16* __restrict__ lo, size_t n8)
{
    size_t i = (size_t)blockIdx.x * blockDim.x + threadIdx.x;
    if (i >= n8) return;
    float4 a = ((const float4*)src)[2 * i];
    float4 b = ((const float4*)src)[2 * i + 1];
    float v[8] = {a.x, a.y, a.z, a.w, b.x, b.y, b.z, b.w};
    uint32_t hw[4], lw[4];
#pragma unroll
    for (int q = 0; q < 4; q++) {
        bf16 h0 = __float2bfloat16(v[2 * q]), h1 = __float2bfloat16(v[2 * q + 1]);
        __nv_bfloat162 hp; hp.x = h0; hp.y = h1;
        hw[q] = *reinterpret_cast<uint32_t*>(&hp);
        __nv_bfloat162 lp;
        lp.x = __float2bfloat16(v[2 * q] - __bfloat162float(h0));
        lp.y = __float2bfloat16(v[2 * q + 1] - __bfloat162float(h1));
        lw[q] = *reinterpret_cast<uint32_t*>(&lp);
    }
    ((uint4*)hi)[i] = make_uint4(hw[0], hw[1], hw[2], hw[3]);
    ((uint4*)lo)[i] = make_uint4(lw[0], lw[1], lw[2], lw[3]);
}

// ---------------------------------------------------------------------------
// Transposed split of memory: memT[b][h][s] = split(memory[s][b][h])
// 64(s) x 32(h) tile; vectorized bf16x2 stores along s.
// ---------------------------------------------------------------------------
__global__ __launch_bounds__(1024) void transpose_split(const float* __restrict__ mem)
{
    __shared__ float t[64][33];
    const int b = blockIdx.z;
    const int s0 = blockIdx.x * 64, h0 = blockIdx.y * 32;
    const int tx = threadIdx.x, ty = threadIdx.y;
    t[ty][tx]      = mem[(size_t)(s0 + ty) * BHd + b * Hd + h0 + tx];
    t[ty + 32][tx] = mem[(size_t)(s0 + 32 + ty) * BHd + b * Hd + h0 + tx];
    __syncthreads();
    const float v0 = t[2 * tx][ty], v1 = t[2 * tx + 1][ty];
    bf16 h0b = __float2bfloat16(v0), h1b = __float2bfloat16(v1);
    __nv_bfloat162 hp; hp.x = h0b; hp.y = h1b;
    __nv_bfloat162 lp;
    lp.x = __float2bfloat16(v0 - __bfloat162float(h0b));
    lp.y = __float2bfloat16(v1 - __bfloat162float(h1b));
    const size_t o = (size_t)b * Hd * Sd + (size_t)(h0 + ty) * Sd + s0 + 2 * tx;
    *(__nv_bfloat162*)(g_memT_hi + o) = hp;
    *(__nv_bfloat162*)(g_memT_lo + o) = lp;
}

// ---------------------------------------------------------------------------
// K2: fused mask + softmax + P-split. Writes attn fp32 and P_hi/P_lo bf16.
// ---------------------------------------------------------------------------
__global__ __launch_bounds__(256) void softmax_split(
    float* __restrict__ attn, const unsigned char* __restrict__ mask,
    bf16* __restrict__ Phi, bf16* __restrict__ Plo)
{
    __shared__ float redmax[8];
    __shared__ float redsum[8];

    const int row = blockIdx.x;
    float* p = attn + (size_t)row * Sd;
    const unsigned char* mp = mask + (size_t)row * Sd;
    const int tid = threadIdx.x;
    const int base = tid * 8;

    float4 v0 = *(const float4*)(p + base);
    float4 v1 = *(const float4*)(p + base + 4);
    unsigned long long mb = *(const unsigned long long*)(mp + base);
    float v[8] = {v0.x, v0.y, v0.z, v0.w, v1.x, v1.y, v1.z, v1.w};
#pragma unroll
    for (int i = 0; i < 8; i++)
        if ((mb >> (8 * i)) & 0xffULL) v[i] = -INFINITY;

    float mx = v[0];
#pragma unroll
    for (int i = 1; i < 8; i++) mx = fmaxf(mx, v[i]);
#pragma unroll
    for (int o = 16; o > 0; o >>= 1)
        mx = fmaxf(mx, __shfl_xor_sync(0xffffffffu, mx, o));
    const int wid = tid >> 5, lane = tid & 31;
    if (lane == 0) redmax[wid] = mx;
    __syncthreads();
    float rmax = redmax[0];
#pragma unroll
    for (int i = 1; i < 8; i++) rmax = fmaxf(rmax, redmax[i]);

    float s = 0.0f;
#pragma unroll
    for (int i = 0; i < 8; i++) {
        v[i] = __expf(v[i] - rmax);
        s += v[i];
    }
#pragma unroll
    for (int o = 16; o > 0; o >>= 1)
        s += __shfl_xor_sync(0xffffffffu, s, o);
    if (lane == 0) redsum[wid] = s;
    __syncthreads();
    float total = 0.0f;
#pragma unroll
    for (int i = 0; i < 8; i++) total += redsum[i];

    const float inv = 1.0f / total;
#pragma unroll
    for (int i = 0; i < 8; i++) v[i] *= inv;
    *(float4*)(p + base)     = make_float4(v[0], v[1], v[2], v[3]);
    *(float4*)(p + base + 4) = make_float4(v[4], v[5], v[6], v[7]);

    // Fused P-split: hi = bf16(v), lo = bf16(v - hi); one uint4 store each.
    uint32_t hw[4], lw[4];
#pragma unroll
    for (int q = 0; q < 4; q++) {
        bf16 h0 = __float2bfloat16(v[2 * q]), h1 = __float2bfloat16(v[2 * q + 1]);
        __nv_bfloat162 hp; hp.x = h0; hp.y = h1;
        hw[q] = *reinterpret_cast<uint32_t*>(&hp);
        __nv_bfloat162 lp;
        lp.x = __float2bfloat16(v[2 * q] - __bfloat162float(h0));
        lp.y = __float2bfloat16(v[2 * q + 1] - __bfloat162float(h1));
        lw[q] = *reinterpret_cast<uint32_t*>(&lp);
    }
    const size_t o16 = ((size_t)row * Sd + base) / 8;  // uint4 index
    ((uint4*)Phi)[o16] = make_uint4(hw[0], hw[1], hw[2], hw[3]);
    ((uint4*)Plo)[o16] = make_uint4(lw[0], lw[1], lw[2], lw[3]);
}

// ---------------------------------------------------------------------------
extern "C" void kernel_launch(void* const* d_in, const int* in_sizes, int n_in,
                              void* d_out, int out_size)
{
    const float* outp = (const float*)d_in[0];                 // (T,B,H)
    const float* mem  = (const float*)d_in[1];                 // (S,B,H)
    const unsigned char* mask = (const unsigned char*)d_in[2]; // (B,T,S)
    const float* W    = (const float*)d_in[3];                 // (H,2H)
    const float* bias = (const float*)d_in[4];                 // (H,)

    float* out  = (float*)d_out;                               // (T,B,H)
    float* attn = out + (size_t)Td * Bd * Hd;                  // (B,T,S)

    void *p_oh, *p_ol, *p_mh, *p_ml, *p_wh, *p_wl, *p_ph, *p_pl;
    cudaGetSymbolAddress(&p_oh, g_out_hi);  cudaGetSymbolAddress(&p_ol, g_out_lo);
    cudaGetSymbolAddress(&p_mh, g_mem_hi);  cudaGetSymbolAddress(&p_ml, g_mem_lo);
    cudaGetSymbolAddress(&p_wh, g_W_hi);    cudaGetSymbolAddress(&p_wl, g_W_lo);
    cudaGetSymbolAddress(&p_ph, g_P_hi);    cudaGetSymbolAddress(&p_pl, g_P_lo);

    cudaFuncSetAttribute(mma_scores, cudaFuncAttributeMaxDynamicSharedMemorySize, SMEM_B);
    cudaFuncSetAttribute(mma_ctx,    cudaFuncAttributeMaxDynamicSharedMemorySize, SMEM_B);
    cudaFuncSetAttribute(mma_linear, cudaFuncAttributeMaxDynamicSharedMemorySize, SMEM_B);

    const size_t nTBH = (size_t)Td * Bd * Hd;
    const size_t nSBH = (size_t)Sd * Bd * Hd;
    const size_t nW   = (size_t)Hd * 2 * Hd;

    split8<<<(unsigned)((nTBH / 8 + 255) / 256), 256>>>(outp, (bf16*)p_oh, (bf16*)p_ol, nTBH / 8);
    split8<<<(unsigned)((nSBH / 8 + 255) / 256), 256>>>(mem, (bf16*)p_mh, (bf16*)p_ml, nSBH / 8);
    transpose_split<<<dim3(Sd / 64, Hd / 32, Bd), dim3(32, 32)>>>(mem);
    split8<<<(unsigned)((nW / 8 + 255) / 256), 256>>>(W, (bf16*)p_wh, (bf16*)p_wl, nW / 8);

    mma_scores<<<dim3(Sd / 128, Td / 128, Bd), 256, SMEM_B>>>(attn);
    softmax_split<<<Bd * Td, 256>>>(attn, mask, (bf16*)p_ph, (bf16*)p_pl);
    mma_ctx<<<dim3(Hd / 128, Td / 128, Bd), 256, SMEM_B>>>();
    mma_linear<<<dim3(Hd / 128, (Td * Bd) / 128), 256, SMEM_B>>>(bias, out);
}

// round 17
// speedup vs baseline: 2.5763x; 1.0105x over previous
#include <cuda_runtime.h>
#include <cuda_bf16.h>
#include <math.h>
#include <stdint.h>

// Problem dims
#define Td 1024
#define Bd 16
#define Hd 1024
#define Sd 2048
#define BHd (Bd*Hd)   // 16384

typedef __nv_bfloat16 bf16;

// ---------------------------------------------------------------------------
// Device-global scratch (no allocs allowed)
// ---------------------------------------------------------------------------
__device__ bf16 g_out_hi[(size_t)Td * Bd * Hd], g_out_lo[(size_t)Td * Bd * Hd];
__device__ bf16 g_mem_hi[(size_t)Sd * Bd * Hd], g_mem_lo[(size_t)Sd * Bd * Hd];
__device__ bf16 g_memT_hi[(size_t)Bd * Hd * Sd], g_memT_lo[(size_t)Bd * Hd * Sd]; // (B,H,S)
__device__ bf16 g_W_hi[(size_t)Hd * 2 * Hd], g_W_lo[(size_t)Hd * 2 * Hd];
__device__ bf16 g_P_hi[(size_t)Bd * Td * Sd], g_P_lo[(size_t)Bd * Td * Sd];
__device__ bf16 g_ctx_hi[(size_t)Td * Bd * Hd], g_ctx_lo[(size_t)Td * Bd * Hd];

// ---------------------------------------------------------------------------
// Helpers
// ---------------------------------------------------------------------------
__device__ __forceinline__ uint32_t s2u(const void* p) {
    uint32_t a;
    asm("{ .reg .u64 t; cvta.to.shared.u64 t, %1; cvt.u32.u64 %0, t; }" : "=r"(a) : "l"(p));
    return a;
}
__device__ __forceinline__ void cpa16(uint32_t s, const void* g) {
    asm volatile("cp.async.cg.shared.global [%0], [%1], 16;" :: "r"(s), "l"(g));
}
__device__ __forceinline__ void cpa_commit() {
    asm volatile("cp.async.commit_group;" ::: "memory");
}
__device__ __forceinline__ void cpa_wait0() {
    asm volatile("cp.async.wait_group 0;" ::: "memory");
}
__device__ __forceinline__ void mma16816(float* c, const uint32_t* a, const uint32_t* b) {
    asm volatile(
        "mma.sync.aligned.m16n8k16.row.col.f32.bf16.bf16.f32 "
        "{%0,%1,%2,%3}, {%4,%5,%6,%7}, {%8,%9}, {%0,%1,%2,%3};"
        : "+f"(c[0]), "+f"(c[1]), "+f"(c[2]), "+f"(c[3])
        : "r"(a[0]), "r"(a[1]), "r"(a[2]), "r"(a[3]), "r"(b[0]), "r"(b[1]));
}

// Tile geometry: 128x128 CTA tile, BK=32 bf16. Rows padded to 80B (40 bf16).
#define TROW 40
#define TILE_B (128 * TROW * 2)      // 10240 B per tile
#define STAGE_B (4 * TILE_B)         // Ah, Al, Bh, Bl
#define SMEM_B (2 * STAGE_B)         // double buffer: 81920 B

// Issue cp.async for one stage. Expressions use `row` (tile row 0..127) and
// `kk0` (k element offset of the 8-element segment within the full K dim).
#define LOAD_STAGE(st, kc, AHI, ALO, BHI, BLO)                               \
    {                                                                        \
        const int c_ = (kc);                                                 \
        _Pragma("unroll")                                                    \
        for (int j_ = 0; j_ < 2; j_++) {                                     \
            const int s_ = j_ * 256 + tid;                                   \
            const int row = s_ >> 2, off_ = s_ & 3;                          \
            const int kk0 = c_ * 32 + off_ * 8;                              \
            const uint32_t so_ = sbase + (st) * STAGE_B + row * 80 + off_ * 16; \
            cpa16(so_,              (const void*)(AHI));                     \
            cpa16(so_ + TILE_B,     (const void*)(ALO));                     \
            cpa16(so_ + 2 * TILE_B, (const void*)(BHI));                     \
            cpa16(so_ + 3 * TILE_B, (const void*)(BLO));                     \
        }                                                                    \
    }

// ---------------------------------------------------------------------------
// Compute one BK=32 stage: 2 k16-steps, 3 split passes (hh, hl, lh).
// Warp tile 64x32: 4 m-tiles (16) x 4 n-tiles (8).
// ---------------------------------------------------------------------------
__device__ __forceinline__ void compute_stage(
    char* sm, int st, int wm, int wn, int lane, float acc[4][4][4])
{
    bf16 (*Ah)[TROW] = (bf16(*)[TROW])(sm + st * STAGE_B);
    bf16 (*Al)[TROW] = (bf16(*)[TROW])(sm + st * STAGE_B + TILE_B);
    bf16 (*Bh)[TROW] = (bf16(*)[TROW])(sm + st * STAGE_B + 2 * TILE_B);
    bf16 (*Bl)[TROW] = (bf16(*)[TROW])(sm + st * STAGE_B + 3 * TILE_B);
    const int g = lane >> 2, i2 = (lane & 3) * 2;
#pragma unroll
    for (int ks = 0; ks < 2; ks++) {
        const int ca = ks * 16 + i2;
        uint32_t bhf[4][2], blf[4][2];
#pragma unroll
        for (int nt = 0; nt < 4; nt++) {
            const int rb = wn * 32 + nt * 8 + g;
            bhf[nt][0] = *(const uint32_t*)&Bh[rb][ca];
            bhf[nt][1] = *(const uint32_t*)&Bh[rb][ca + 8];
            blf[nt][0] = *(const uint32_t*)&Bl[rb][ca];
            blf[nt][1] = *(const uint32_t*)&Bl[rb][ca + 8];
        }
#pragma unroll
        for (int mt = 0; mt < 4; mt++) {
            const int ra = wm * 64 + mt * 16 + g;
            uint32_t ahf[4] = {
                *(const uint32_t*)&Ah[ra][ca],     *(const uint32_t*)&Ah[ra + 8][ca],
                *(const uint32_t*)&Ah[ra][ca + 8], *(const uint32_t*)&Ah[ra + 8][ca + 8]};
            uint32_t alf[4] = {
                *(const uint32_t*)&Al[ra][ca],     *(const uint32_t*)&Al[ra + 8][ca],
                *(const uint32_t*)&Al[ra][ca + 8], *(const uint32_t*)&Al[ra + 8][ca + 8]};
#pragma unroll
            for (int nt = 0; nt < 4; nt++) {
                mma16816(acc[mt][nt], ahf, bhf[nt]);
                mma16816(acc[mt][nt], ahf, blf[nt]);
                mma16816(acc[mt][nt], alf, bhf[nt]);
            }
        }
    }
}

#define MMA_PRE()                                                             \
    extern __shared__ char sm[];                                              \
    const uint32_t sbase = s2u(sm);                                           \
    const int tid = threadIdx.x, wid = tid >> 5, lane = tid & 31;             \
    const int wm = wid >> 2, wn = wid & 3;                                    \
    const int g = lane >> 2, i2 = (lane & 3) * 2;                             \
    float acc[4][4][4];                                                       \
    _Pragma("unroll")                                                         \
    for (int a_ = 0; a_ < 4; a_++)                                            \
        _Pragma("unroll")                                                     \
        for (int b_ = 0; b_ < 4; b_++)                                        \
            _Pragma("unroll")                                                 \
            for (int c2_ = 0; c2_ < 4; c2_++) acc[a_][b_][c2_] = 0.0f;

// ---------------------------------------------------------------------------
// K1: scores[b,t,s] = sum_h out*mem  (K=1024, 32 chunks)
// ---------------------------------------------------------------------------
__global__ __launch_bounds__(256, 2) void mma_scores(float* __restrict__ attn)
{
    const int b = blockIdx.z, m0 = blockIdx.y * 128, n0 = blockIdx.x * 128;
    MMA_PRE()
    LOAD_STAGE(0, 0,
        g_out_hi + ((size_t)(m0 + row) * BHd + b * Hd + kk0),
        g_out_lo + ((size_t)(m0 + row) * BHd + b * Hd + kk0),
        g_mem_hi + ((size_t)(n0 + row) * BHd + b * Hd + kk0),
        g_mem_lo + ((size_t)(n0 + row) * BHd + b * Hd + kk0))
    cpa_commit();
    int buf = 0;
    for (int c = 0; c < 32; c++) {
        cpa_wait0();
        __syncthreads();
        if (c + 1 < 32) {
            LOAD_STAGE(buf ^ 1, c + 1,
                g_out_hi + ((size_t)(m0 + row) * BHd + b * Hd + kk0),
                g_out_lo + ((size_t)(m0 + row) * BHd + b * Hd + kk0),
                g_mem_hi + ((size_t)(n0 + row) * BHd + b * Hd + kk0),
                g_mem_lo + ((size_t)(n0 + row) * BHd + b * Hd + kk0))
        }
        cpa_commit();
        compute_stage(sm, buf, wm, wn, lane, acc);
        buf ^= 1;
    }
#pragma unroll
    for (int mt = 0; mt < 4; mt++)
#pragma unroll
        for (int nt = 0; nt < 4; nt++) {
            const int r0 = m0 + wm * 64 + mt * 16 + g;
            const int cc = n0 + wn * 32 + nt * 8 + i2;
            float* p = attn + (size_t)b * Td * Sd + (size_t)r0 * Sd + cc;
            *(float2*)p = make_float2(acc[mt][nt][0], acc[mt][nt][1]);
            *(float2*)(p + 8 * Sd) = make_float2(acc[mt][nt][2], acc[mt][nt][3]);
        }
}

// ---------------------------------------------------------------------------
// K3: ctx = P*mem; epilogue converts accumulators straight to bf16 hi/lo
// ---------------------------------------------------------------------------
__global__ __launch_bounds__(256, 2) void mma_ctx()
{
    const int b = blockIdx.z, m0 = blockIdx.y * 128, n0 = blockIdx.x * 128;
    MMA_PRE()
    LOAD_STAGE(0, 0,
        g_P_hi + ((size_t)b * Td * Sd + (size_t)(m0 + row) * Sd + kk0),
        g_P_lo + ((size_t)b * Td * Sd + (size_t)(m0 + row) * Sd + kk0),
        g_memT_hi + ((size_t)b * Hd * Sd + (size_t)(n0 + row) * Sd + kk0),
        g_memT_lo + ((size_t)b * Hd * Sd + (size_t)(n0 + row) * Sd + kk0))
    cpa_commit();
    int buf = 0;
    for (int c = 0; c < 64; c++) {
        cpa_wait0();
        __syncthreads();
        if (c + 1 < 64) {
            LOAD_STAGE(buf ^ 1, c + 1,
                g_P_hi + ((size_t)b * Td * Sd + (size_t)(m0 + row) * Sd + kk0),
                g_P_lo + ((size_t)b * Td * Sd + (size_t)(m0 + row) * Sd + kk0),
                g_memT_hi + ((size_t)b * Hd * Sd + (size_t)(n0 + row) * Sd + kk0),
                g_memT_lo + ((size_t)b * Hd * Sd + (size_t)(n0 + row) * Sd + kk0))
        }
        cpa_commit();
        compute_stage(sm, buf, wm, wn, lane, acc);
        buf ^= 1;
    }
#pragma unroll
    for (int mt = 0; mt < 4; mt++)
#pragma unroll
        for (int nt = 0; nt < 4; nt++) {
            const int r0 = m0 + wm * 64 + mt * 16 + g;   // t
            const int cc = n0 + wn * 32 + nt * 8 + i2;   // h
            float v0 = acc[mt][nt][0], v1 = acc[mt][nt][1];
            float v2 = acc[mt][nt][2], v3 = acc[mt][nt][3];
            bf16 h0 = __float2bfloat16(v0), h1 = __float2bfloat16(v1);
            bf16 h2 = __float2bfloat16(v2), h3 = __float2bfloat16(v3);
            const size_t o  = (size_t)r0 * BHd + b * Hd + cc;
            const size_t o8 = o + (size_t)8 * BHd;
            __nv_bfloat162 hp0; hp0.x = h0; hp0.y = h1;
            __nv_bfloat162 hp1; hp1.x = h2; hp1.y = h3;
            *(__nv_bfloat162*)(g_ctx_hi + o)  = hp0;
            *(__nv_bfloat162*)(g_ctx_hi + o8) = hp1;
            __nv_bfloat162 lp0, lp1;
            lp0.x = __float2bfloat16(v0 - __bfloat162float(h0));
            lp0.y = __float2bfloat16(v1 - __bfloat162float(h1));
            lp1.x = __float2bfloat16(v2 - __bfloat162float(h2));
            lp1.y = __float2bfloat16(v3 - __bfloat162float(h3));
            *(__nv_bfloat162*)(g_ctx_lo + o)  = lp0;
            *(__nv_bfloat162*)(g_ctx_lo + o8) = lp1;
        }
}

// ---------------------------------------------------------------------------
// K4: out[r,n] = tanh(bias + sum_d [ctx|out]*W)  (K=2048, 64 chunks)
// ---------------------------------------------------------------------------
__global__ __launch_bounds__(256, 2) void mma_linear(
    const float* __restrict__ bias, float* __restrict__ out)
{
    const int m0 = blockIdx.y * 128, n0 = blockIdx.x * 128;
    MMA_PRE()
    LOAD_STAGE(0, 0,
        ((kk0 < Hd) ? (g_ctx_hi + ((size_t)(m0 + row) * Hd + kk0))
                    : (g_out_hi + ((size_t)(m0 + row) * Hd + (kk0 - Hd)))),
        ((kk0 < Hd) ? (g_ctx_lo + ((size_t)(m0 + row) * Hd + kk0))
                    : (g_out_lo + ((size_t)(m0 + row) * Hd + (kk0 - Hd)))),
        g_W_hi + ((size_t)(n0 + row) * (2 * Hd) + kk0),
        g_W_lo + ((size_t)(n0 + row) * (2 * Hd) + kk0))
    cpa_commit();
    int buf = 0;
    for (int c = 0; c < 64; c++) {
        cpa_wait0();
        __syncthreads();
        if (c + 1 < 64) {
            LOAD_STAGE(buf ^ 1, c + 1,
                ((kk0 < Hd) ? (g_ctx_hi + ((size_t)(m0 + row) * Hd + kk0))
                            : (g_out_hi + ((size_t)(m0 + row) * Hd + (kk0 - Hd)))),
                ((kk0 < Hd) ? (g_ctx_lo + ((size_t)(m0 + row) * Hd + kk0))
                            : (g_out_lo + ((size_t)(m0 + row) * Hd + (kk0 - Hd)))),
                g_W_hi + ((size_t)(n0 + row) * (2 * Hd) + kk0),
                g_W_lo + ((size_t)(n0 + row) * (2 * Hd) + kk0))
        }
        cpa_commit();
        compute_stage(sm, buf, wm, wn, lane, acc);
        buf ^= 1;
    }
#pragma unroll
    for (int mt = 0; mt < 4; mt++)
#pragma unroll
        for (int nt = 0; nt < 4; nt++) {
            const int r0 = m0 + wm * 64 + mt * 16 + g;
            const int cc = n0 + wn * 32 + nt * 8 + i2;
            const float b0 = bias[cc], b1 = bias[cc + 1];
            float* p = out + (size_t)r0 * Hd + cc;
            *(float2*)p = make_float2(tanhf(acc[mt][nt][0] + b0), tanhf(acc[mt][nt][1] + b1));
            *(float2*)(p + 8 * Hd) =
                make_float2(tanhf(acc[mt][nt][2] + b0), tanhf(acc[mt][nt][3] + b1));
        }
}

// ---------------------------------------------------------------------------
// prep_split: fused hi/lo splits of output, memory, W (one launch).
// Block ranges: [0, NB_OUT) out, [NB_OUT, NB_OUT+NB_MEM) mem, rest W.
// ---------------------------------------------------------------------------
#define NB_OUT 8192u   // (T*B*H/8)/256
#define NB_MEM 16384u  // (S*B*H/8)/256
#define NB_W   1024u   // (H*2H/8)/256

__device__ __forceinline__ void split8_body(const float* __restrict__ src,
                                            bf16* __restrict__ hi,
                                            bf16* __restrict__ lo, size_t i)
{
    float4 a = ((const float4*)src)[2 * i];
    float4 b = ((const float4*)src)[2 * i + 1];
    float v[8] = {a.x, a.y, a.z, a.w, b.x, b.y, b.z, b.w};
    uint32_t hw[4], lw[4];
#pragma unroll
    for (int q = 0; q < 4; q++) {
        bf16 h0 = __float2bfloat16(v[2 * q]), h1 = __float2bfloat16(v[2 * q + 1]);
        __nv_bfloat162 hp; hp.x = h0; hp.y = h1;
        hw[q] = *reinterpret_cast<uint32_t*>(&hp);
        __nv_bfloat162 lp;
        lp.x = __float2bfloat16(v[2 * q] - __bfloat162float(h0));
        lp.y = __float2bfloat16(v[2 * q + 1] - __bfloat162float(h1));
        lw[q] = *reinterpret_cast<uint32_t*>(&lp);
    }
    ((uint4*)hi)[i] = make_uint4(hw[0], hw[1], hw[2], hw[3]);
    ((uint4*)lo)[i] = make_uint4(lw[0], lw[1], lw[2], lw[3]);
}

__global__ __launch_bounds__(256) void prep_split(
    const float* __restrict__ outp, const float* __restrict__ mem,
    const float* __restrict__ W)
{
    const unsigned bid = blockIdx.x;
    if (bid < NB_OUT) {
        const size_t i = (size_t)bid * 256 + threadIdx.x;
        split8_body(outp, g_out_hi, g_out_lo, i);
    } else if (bid < NB_OUT + NB_MEM) {
        const size_t i = (size_t)(bid - NB_OUT) * 256 + threadIdx.x;
        split8_body(mem, g_mem_hi, g_mem_lo, i);
    } else {
        const size_t i = (size_t)(bid - NB_OUT - NB_MEM) * 256 + threadIdx.x;
        split8_body(W, g_W_hi, g_W_lo, i);
    }
}

// ---------------------------------------------------------------------------
// Transposed split of memory: memT[b][h][s] = split(memory[s][b][h])
// 64(s) x 32(h) tile; vectorized bf16x2 stores along s.
// ---------------------------------------------------------------------------
__global__ __launch_bounds__(1024) void transpose_split(const float* __restrict__ mem)
{
    __shared__ float t[64][33];
    const int b = blockIdx.z;
    const int s0 = blockIdx.x * 64, h0 = blockIdx.y * 32;
    const int tx = threadIdx.x, ty = threadIdx.y;
    t[ty][tx]      = mem[(size_t)(s0 + ty) * BHd + b * Hd + h0 + tx];
    t[ty + 32][tx] = mem[(size_t)(s0 + 32 + ty) * BHd + b * Hd + h0 + tx];
    __syncthreads();
    const float v0 = t[2 * tx][ty], v1 = t[2 * tx + 1][ty];
    bf16 h0b = __float2bfloat16(v0), h1b = __float2bfloat16(v1);
    __nv_bfloat162 hp; hp.x = h0b; hp.y = h1b;
    __nv_bfloat162 lp;
    lp.x = __float2bfloat16(v0 - __bfloat162float(h0b));
    lp.y = __float2bfloat16(v1 - __bfloat162float(h1b));
    const size_t o = (size_t)b * Hd * Sd + (size_t)(h0 + ty) * Sd + s0 + 2 * tx;
    *(__nv_bfloat162*)(g_memT_hi + o) = hp;
    *(__nv_bfloat162*)(g_memT_lo + o) = lp;
}

// ---------------------------------------------------------------------------
// K2: fused mask + softmax + P-split. Writes attn fp32 and P_hi/P_lo bf16.
// ---------------------------------------------------------------------------
__global__ __launch_bounds__(256) void softmax_split(
    float* __restrict__ attn, const unsigned char* __restrict__ mask,
    bf16* __restrict__ Phi, bf16* __restrict__ Plo)
{
    __shared__ float redmax[8];
    __shared__ float redsum[8];

    const int row = blockIdx.x;
    float* p = attn + (size_t)row * Sd;
    const unsigned char* mp = mask + (size_t)row * Sd;
    const int tid = threadIdx.x;
    const int base = tid * 8;

    float4 v0 = *(const float4*)(p + base);
    float4 v1 = *(const float4*)(p + base + 4);
    unsigned long long mb = *(const unsigned long long*)(mp + base);
    float v[8] = {v0.x, v0.y, v0.z, v0.w, v1.x, v1.y, v1.z, v1.w};
#pragma unroll
    for (int i = 0; i < 8; i++)
        if ((mb >> (8 * i)) & 0xffULL) v[i] = -INFINITY;

    float mx = v[0];
#pragma unroll
    for (int i = 1; i < 8; i++) mx = fmaxf(mx, v[i]);
#pragma unroll
    for (int o = 16; o > 0; o >>= 1)
        mx = fmaxf(mx, __shfl_xor_sync(0xffffffffu, mx, o));
    const int wid = tid >> 5, lane = tid & 31;
    if (lane == 0) redmax[wid] = mx;
    __syncthreads();
    float rmax = redmax[0];
#pragma unroll
    for (int i = 1; i < 8; i++) rmax = fmaxf(rmax, redmax[i]);

    float s = 0.0f;
#pragma unroll
    for (int i = 0; i < 8; i++) {
        v[i] = __expf(v[i] - rmax);
        s += v[i];
    }
#pragma unroll
    for (int o = 16; o > 0; o >>= 1)
        s += __shfl_xor_sync(0xffffffffu, s, o);
    if (lane == 0) redsum[wid] = s;
    __syncthreads();
    float total = 0.0f;
#pragma unroll
    for (int i = 0; i < 8; i++) total += redsum[i];

    const float inv = 1.0f / total;
#pragma unroll
    for (int i = 0; i < 8; i++) v[i] *= inv;
    *(float4*)(p + base)     = make_float4(v[0], v[1], v[2], v[3]);
    *(float4*)(p + base + 4) = make_float4(v[4], v[5], v[6], v[7]);

    uint32_t hw[4], lw[4];
#pragma unroll
    for (int q = 0; q < 4; q++) {
        bf16 h0 = __float2bfloat16(v[2 * q]), h1 = __float2bfloat16(v[2 * q + 1]);
        __nv_bfloat162 hp; hp.x = h0; hp.y = h1;
        hw[q] = *reinterpret_cast<uint32_t*>(&hp);
        __nv_bfloat162 lp;
        lp.x = __float2bfloat16(v[2 * q] - __bfloat162float(h0));
        lp.y = __float2bfloat16(v[2 * q + 1] - __bfloat162float(h1));
        lw[q] = *reinterpret_cast<uint32_t*>(&lp);
    }
    const size_t o16 = ((size_t)row * Sd + base) / 8;  // uint4 index
    ((uint4*)Phi)[o16] = make_uint4(hw[0], hw[1], hw[2], hw[3]);
    ((uint4*)Plo)[o16] = make_uint4(lw[0], lw[1], lw[2], lw[3]);
}

// ---------------------------------------------------------------------------
extern "C" void kernel_launch(void* const* d_in, const int* in_sizes, int n_in,
                              void* d_out, int out_size)
{
    const float* outp = (const float*)d_in[0];                 // (T,B,H)
    const float* mem  = (const float*)d_in[1];                 // (S,B,H)
    const unsigned char* mask = (const unsigned char*)d_in[2]; // (B,T,S)
    const float* W    = (const float*)d_in[3];                 // (H,2H)
    const float* bias = (const float*)d_in[4];                 // (H,)

    float* out  = (float*)d_out;                               // (T,B,H)
    float* attn = out + (size_t)Td * Bd * Hd;                  // (B,T,S)

    void *p_ph, *p_pl;
    cudaGetSymbolAddress(&p_ph, g_P_hi);
    cudaGetSymbolAddress(&p_pl, g_P_lo);

    cudaFuncSetAttribute(mma_scores, cudaFuncAttributeMaxDynamicSharedMemorySize, SMEM_B);
    cudaFuncSetAttribute(mma_ctx,    cudaFuncAttributeMaxDynamicSharedMemorySize, SMEM_B);
    cudaFuncSetAttribute(mma_linear, cudaFuncAttributeMaxDynamicSharedMemorySize, SMEM_B);

    prep_split<<<NB_OUT + NB_MEM + NB_W, 256>>>(outp, mem, W);
    transpose_split<<<dim3(Sd / 64, Hd / 32, Bd), dim3(32, 32)>>>(mem);

    mma_scores<<<dim3(Sd / 128, Td / 128, Bd), 256, SMEM_B>>>(attn);
    softmax_split<<<Bd * Td, 256>>>(attn, mask, (bf16*)p_ph, (bf16*)p_pl);
    mma_ctx<<<dim3(Hd / 128, Td / 128, Bd), 256, SMEM_B>>>();
    mma_linear<<<dim3(Hd / 128, (Td * Bd) / 128), 256, SMEM_B>>>(bias, out);
}